// round 16
// baseline (speedup 1.0000x reference)
#include <cuda_runtime.h>
#include <cuda_bf16.h>
#include <math.h>
#include <stdint.h>

#define BN    32
#define NODES 202
#define NI    200
#define DD    64
#define JT    8
#define NJT   25
#define EPS   1e-5f
#define SLOPE 0.01f

typedef unsigned long long u64;

// ---- packed fp32x2 helpers (sm_103a) ----
__device__ __forceinline__ u64 f2_mul(u64 a, u64 b) {
    u64 r; asm("mul.rn.f32x2 %0,%1,%2;" : "=l"(r) : "l"(a), "l"(b)); return r;
}
__device__ __forceinline__ u64 f2_add(u64 a, u64 b) {
    u64 r; asm("add.rn.f32x2 %0,%1,%2;" : "=l"(r) : "l"(a), "l"(b)); return r;
}
__device__ __forceinline__ u64 f2_fma(u64 a, u64 b, u64 c) {
    u64 r; asm("fma.rn.f32x2 %0,%1,%2,%3;" : "=l"(r) : "l"(a), "l"(b), "l"(c)); return r;
}
__device__ __forceinline__ u64 f2_pack(float lo, float hi) {
    u64 r; asm("mov.b64 %0,{%1,%2};" : "=l"(r) : "f"(lo), "f"(hi)); return r;
}
__device__ __forceinline__ void f2_unpack(u64 v, float& lo, float& hi) {
    asm("mov.b64 {%0,%1},%2;" : "=f"(lo), "=f"(hi) : "l"(v));
}

// ---- warp-level bf16 MMA (legacy HMMA path; compiles for plain sm_103) ----
__device__ __forceinline__ void mma_bf16(float& d0, float& d1, float& d2, float& d3,
                                         uint32_t a0, uint32_t a1, uint32_t a2, uint32_t a3,
                                         uint32_t b0, uint32_t b1) {
    asm volatile(
        "mma.sync.aligned.m16n8k16.row.col.f32.bf16.bf16.f32 "
        "{%0,%1,%2,%3},{%4,%5,%6,%7},{%8,%9},{%0,%1,%2,%3};"
        : "+f"(d0), "+f"(d1), "+f"(d2), "+f"(d3)
        : "r"(a0), "r"(a1), "r"(a2), "r"(a3), "r"(b0), "r"(b1));
}
__device__ __forceinline__ uint32_t bf2pack(float x, float y) {
    __nv_bfloat162 p = __floats2bfloat162_rn(x, y);
    return *(uint32_t*)&p;
}

// ---------------- device scratch ----------------
__device__ float  g_ua[BN * NI * DD];
__device__ float  g_qk[BN * 4 * NI];
__device__ float  g_prm[BN * NI * 8];                    // (q1,k1,iZ1,q2),(k2,iZ2,_,_)
__device__ __align__(16) float4 g_cT[BN * NJT * 4 * NI]; // c planes (k3b smem layout)
__device__ float  g_S0[BN * NJT * 16];                   // Sc layout: [jj*2+head]
// packed bf16x2 operands: [b][buf 0=uahi 1=ualo 2=whi 3=wlo][i][c]  (c: 32 words/row)
__device__ uint32_t g_pk[BN * 4 * NI * 32];

// =======================================================================
// kA1: per-batch-half prep. grid (2, BN), 256 threads.
#define B_W    0
#define B_A    8192
#define B_WB   8576
#define B_LNW  8704
#define B_LNB  8768
#define B_RAW  8832
#define B_UA   15768
#define B_MU   22568
#define B_RS   22670
#define B_UID  22772
#define B_IID  22836
#define B_VQ   22900
#define B_VK   23028
#define B_RED  23156
#define B_CQK  23164
#define B_QC   23170
#define B_KC   23172
#define B_FLOATS 23174
#define B_BYTES  (B_FLOATS * 4)

extern __shared__ float smB[];

__global__ __launch_bounds__(256, 1)
void kA1_prep(const float* __restrict__ emb,
              const float* __restrict__ lnw, const float* __restrict__ lnb,
              const float* __restrict__ W1, const float* __restrict__ W1b,
              const float* __restrict__ W2, const float* __restrict__ W2b,
              const float* __restrict__ a1, const float* __restrict__ a1b,
              const float* __restrict__ a2, const float* __restrict__ a2b,
              float* __restrict__ out) {
    int h    = blockIdx.x;
    int b    = blockIdx.y;
    int t    = threadIdx.x;
    int warp = t >> 5, lane = t & 31;

    float* W_s   = smB + B_W;
    float* a_s   = smB + B_A;
    float* wb_s  = smB + B_WB;
    float* lnw_s = smB + B_LNW;
    float* lnb_s = smB + B_LNB;
    float* raw   = smB + B_RAW;
    float* ua_s  = smB + B_UA;
    float* mu_s  = smB + B_MU;
    float* rs_s  = smB + B_RS;
    float* uid   = smB + B_UID;
    float* iid   = smB + B_IID;
    float* vq_s  = smB + B_VQ;
    float* vk_s  = smB + B_VK;
    float* red   = smB + B_RED;
    float* cqk   = smB + B_CQK;
    float* qc_s  = smB + B_QC;
    float* kc_s  = smB + B_KC;

    for (int idx = t; idx < 2048; idx += 256) {
        int hh = idx >> 10;
        ((float4*)W_s)[idx] = ((const float4*)(hh ? W2 : W1))[idx & 1023];
    }
    for (int idx = t; idx < 384; idx += 256)
        a_s[idx] = (idx < 192) ? a1[idx] : a2[idx - 192];
    if (t < 128) wb_s[t] = (t < 64) ? W1b[t] : W2b[t - 64];
    if (t < 64) { lnw_s[t] = lnw[t]; lnb_s[t] = lnb[t]; }
    const float4* e4 = (const float4*)(emb + (size_t)b * NODES * DD);
    for (int idx = t; idx < 102 * 16; idx += 256) {
        int r = idx >> 4, c = idx & 15;
        int g = (r < 2) ? r : r + 100 * h;
        *(float4*)(raw + r * 68 + c * 4) = e4[g * 16 + c];
    }
    __syncthreads();

    if (t < 102) {
        const float* rp = raw + t * 68;
        float s = 0.f, ss = 0.f;
        #pragma unroll
        for (int c = 0; c < 16; c++) {
            float4 v = *(const float4*)(rp + c * 4);
            s += (v.x + v.y) + (v.z + v.w);
            ss = fmaf(v.x, v.x, fmaf(v.y, v.y, fmaf(v.z, v.z, fmaf(v.w, v.w, ss))));
        }
        float m = s * (1.f / DD);
        float var = fmaf(-m, m, ss * (1.f / DD));
        mu_s[t] = m;
        rs_s[t] = rsqrtf(var + EPS);
    }
    if (t >= 208 && t < 214) {
        int idx = t - 208, hh = idx / 3, wch = idx % 3;
        float s = 0.f;
        #pragma unroll 8
        for (int o = 0; o < DD; o++)
            s = fmaf(a_s[hh * 192 + wch * 64 + o], wb_s[hh * 64 + o], s);
        cqk[idx] = s;
    }
    __syncthreads();

    if (t < 128) {
        int rw = t >> 6, d = t & 63;
        float v = fmaf((raw[rw * 68 + d] - mu_s[rw]) * rs_s[rw], lnw_s[d], lnb_s[d]);
        (rw ? iid : uid)[d] = v;
    }
    __syncthreads();
    if (h == 0 && t < DD) {
        float u = uid[t] * iid[t];
        out[(size_t)(b * 201) * DD + t] = u > 0.f ? u : SLOPE * u;
    }

    for (int idx = t; idx < 100 * 16; idx += 256) {
        int r = idx >> 4, c = idx & 15;
        float4 v = *(const float4*)(raw + (r + 2) * 68 + c * 4);
        float m = mu_s[r + 2], sc = rs_s[r + 2];
        float4 w4 = *(const float4*)(lnw_s + c * 4);
        float4 b4 = *(const float4*)(lnb_s + c * 4);
        float4 u4 = *(const float4*)(uid + c * 4);
        float4 o4;
        o4.x = fmaf((v.x - m) * sc, w4.x, b4.x) * u4.x;
        o4.y = fmaf((v.y - m) * sc, w4.y, b4.y) * u4.y;
        o4.z = fmaf((v.z - m) * sc, w4.z, b4.z) * u4.z;
        o4.w = fmaf((v.w - m) * sc, w4.w, b4.w) * u4.w;
        *(float4*)(ua_s + r * 68 + c * 4) = o4;
        ((float4*)(g_ua + ((size_t)b * NI + 100 * h + r) * DD))[c] = o4;
    }
    __syncthreads();

    // ---- write packed bf16 operands for k3a (own 100 rows) ----
    {
        uint32_t* pk = g_pk + (size_t)b * 4 * NI * 32;
        for (int idx = t; idx < 100 * 32; idx += 256) {
            int r = idx >> 5, c = idx & 31;
            float2 x = *(const float2*)(ua_s + r * 68 + c * 2);
            __nv_bfloat16 h0 = __float2bfloat16(x.x);
            __nv_bfloat16 h1 = __float2bfloat16(x.y);
            float r0 = x.x - __bfloat162float(h0);
            float r1 = x.y - __bfloat162float(h1);
            float w0f = x.x * x.x, w1f = x.y * x.y;
            __nv_bfloat16 wh0 = __float2bfloat16(w0f);
            __nv_bfloat16 wh1 = __float2bfloat16(w1f);
            float wr0 = w0f - __bfloat162float(wh0);
            float wr1 = w1f - __bfloat162float(wh1);
            int gi = (100 * h + r) * 32 + c;
            pk[gi]                = ((uint32_t)*(unsigned short*)&h1 << 16) | *(unsigned short*)&h0;
            pk[NI * 32 + gi]      = bf2pack(r0, r1);
            pk[2 * NI * 32 + gi]  = ((uint32_t)*(unsigned short*)&wh1 << 16) | *(unsigned short*)&wh0;
            pk[3 * NI * 32 + gi]  = bf2pack(wr0, wr1);
        }
    }

    if (t < 128) {
        int hh = t >> 6, d = t & 63;
        const float* Wp = W_s + hh * 4096 + d;
        const float* ap = a_s + hh * 192;
        float sqv = 0.f, skv = 0.f, siv = 0.f;
        #pragma unroll 8
        for (int o = 0; o < DD; o++) {
            float wv = Wp[o * 64];
            sqv = fmaf(ap[o],       wv, sqv);
            skv = fmaf(ap[64 + o],  wv, skv);
            siv = fmaf(ap[128 + o], wv, siv);
        }
        vq_s[hh * 64 + d] = sqv;
        vk_s[hh * 64 + d] = skv;
        float viid = siv * iid[d];
        #pragma unroll
        for (int o = 16; o > 0; o >>= 1) viid += __shfl_xor_sync(0xffffffffu, viid, o);
        if (lane == 0) red[warp] = viid;
    }
    __syncthreads();
    if (t == 0) {
        qc_s[0] = red[0] + red[1] + cqk[0] + cqk[2] + a1b[0];
        kc_s[0] = cqk[1];
        qc_s[1] = red[2] + red[3] + cqk[3] + cqk[5] + a2b[0];
        kc_s[1] = cqk[4];
    }
    __syncthreads();

    if (t < 100) {
        const float* u = ua_s + t * 68;
        float s10 = 0, s20 = 0, s11 = 0, s21 = 0;
        #pragma unroll
        for (int c = 0; c < 16; c++) {
            float4 uv = *(const float4*)(u + c * 4);
            float4 q0 = *(const float4*)(vq_s + c * 4);
            float4 k0 = *(const float4*)(vk_s + c * 4);
            float4 q1v = *(const float4*)(vq_s + 64 + c * 4);
            float4 k1v = *(const float4*)(vk_s + 64 + c * 4);
            s10 = fmaf(uv.x, q0.x, fmaf(uv.y, q0.y, fmaf(uv.z, q0.z, fmaf(uv.w, q0.w, s10))));
            s20 = fmaf(uv.x, k0.x, fmaf(uv.y, k0.y, fmaf(uv.z, k0.z, fmaf(uv.w, k0.w, s20))));
            s11 = fmaf(uv.x, q1v.x, fmaf(uv.y, q1v.y, fmaf(uv.z, q1v.z, fmaf(uv.w, q1v.w, s11))));
            s21 = fmaf(uv.x, k1v.x, fmaf(uv.y, k1v.y, fmaf(uv.z, k1v.z, fmaf(uv.w, k1v.w, s21))));
        }
        int i = 100 * h + t;
        float* gq = g_qk + (size_t)b * 800;
        gq[i]       = s10 + qc_s[0];
        gq[200 + i] = s20 + kc_s[0];
        gq[400 + i] = s11 + qc_s[1];
        gq[600 + i] = s21 + kc_s[1];
    }
}

// =======================================================================
// kA2: softmax Z. grid (4, BN).
__global__ __launch_bounds__(256, 8)
void kA2_z() {
    __shared__ float s_qk[800];
    __shared__ float zp[400];
    int q = blockIdx.x;
    int b = blockIdx.y;
    int t = threadIdx.x;

    const float* gq = g_qk + (size_t)b * 800;
    for (int idx = t; idx < 800; idx += 256) s_qk[idx] = gq[idx];
    __syncthreads();

    if (t < 200) {
        int seg = t / 50, il = t % 50;
        int i = q * 50 + il;
        float q1 = s_qk[i], q2 = s_qk[400 + i];
        float Z1 = 0.f, Z2 = 0.f;
        int j0 = seg * 50;
        #pragma unroll 5
        for (int jj = 0; jj < 50; jj++) {
            int j = j0 + jj;
            float s = q1 + s_qk[200 + j]; s = s > 0.f ? s : SLOPE * s; Z1 += __expf(s);
            float r = q2 + s_qk[600 + j]; r = r > 0.f ? r : SLOPE * r; Z2 += __expf(r);
        }
        zp[seg * 50 + il]       = Z1;
        zp[200 + seg * 50 + il] = Z2;
    }
    __syncthreads();
    if (t < 50) {
        int i = q * 50 + t;
        float Z1 = zp[t] + zp[50 + t] + zp[100 + t] + zp[150 + t];
        float Z2 = zp[200 + t] + zp[250 + t] + zp[300 + t] + zp[350 + t];
        float4* p = (float4*)(g_prm + (size_t)(b * NI + i) * 8);
        p[0] = make_float4(s_qk[i], s_qk[200 + i], 1.f / Z1, s_qk[400 + i]);
        p[1] = make_float4(s_qk[600 + i], 1.f / Z2, 0.f, 0.f);
    }
}

// =======================================================================
// kA3: S0[j] = sum_i alpha_ij  (column sums).  grid (4, BN).
__global__ __launch_bounds__(256, 8)
void kA3_s0() {
    __shared__ float s_qk[800];
    __shared__ float s_iz[400];
    __shared__ float zp[400];
    int q = blockIdx.x;
    int b = blockIdx.y;
    int t = threadIdx.x;

    const float* gq = g_qk + (size_t)b * 800;
    for (int idx = t; idx < 800; idx += 256) s_qk[idx] = gq[idx];
    if (t < 200) {
        const float4* pp = (const float4*)(g_prm + (size_t)(b * NI + t) * 8);
        s_iz[t]       = pp[0].z;
        s_iz[200 + t] = pp[1].y;
    }
    __syncthreads();

    if (t < 200) {
        int seg = t / 50, jl = t % 50;
        int j = q * 50 + jl;
        float k1 = s_qk[200 + j], k2 = s_qk[600 + j];
        float S1 = 0.f, S2 = 0.f;
        int i0 = seg * 50;
        #pragma unroll 5
        for (int ii = 0; ii < 50; ii++) {
            int i = i0 + ii;
            float s = s_qk[i] + k1;       s = s > 0.f ? s : SLOPE * s;
            S1 = fmaf(__expf(s), s_iz[i], S1);
            float r = s_qk[400 + i] + k2; r = r > 0.f ? r : SLOPE * r;
            S2 = fmaf(__expf(r), s_iz[200 + i], S2);
        }
        zp[seg * 50 + jl]       = S1;
        zp[200 + seg * 50 + jl] = S2;
    }
    __syncthreads();
    if (t < 100) {
        int head = t / 50, jl = t % 50;
        int j = q * 50 + jl;
        int o = head * 200;
        float S = zp[o + jl] + zp[o + 50 + jl] + zp[o + 100 + jl] + zp[o + 150 + jl];
        g_S0[((size_t)b * NJT + (j >> 3)) * 16 + (j & 7) * 2 + head] = S;
    }
}

// =======================================================================
// k3a v3: phased Gram with precomputed packs (pure copy staging).
// grid (2, 4, BN), 256 threads, 62.4 KB smem, 3 blocks/SM.
#define GSTR    36
#define GA_HI   0
#define GA_LO   28800
#define GA_KK1  57600
#define GA_KK2  58400
#define GA_QZ   59200
#define GA_BYTES 62400

extern __shared__ __align__(16) char smg[];

__global__ __launch_bounds__(256, 3)
void k3a_gram() {
    int mt = blockIdx.x;
    int ns = blockIdx.y;
    int b  = blockIdx.z;
    int t  = threadIdx.x;
    int warp = t >> 5, lane = t & 31;
    int g = lane >> 2, tg = lane & 3;

    uint32_t* hi = (uint32_t*)(smg + GA_HI);
    uint32_t* lo = (uint32_t*)(smg + GA_LO);
    float*    kk1 = (float*)(smg + GA_KK1);
    float*    kk2 = (float*)(smg + GA_KK2);
    float4*   qz  = (float4*)(smg + GA_QZ);

    int nt0 = (ns == 0) ? 0 : 1 + ns * 6;   // 0,7,13,19
    int cnt = (ns == 0) ? 7 : 6;

    const uint32_t* pk = g_pk + (size_t)b * 4 * NI * 32;

    // ---- Phase A staging: ua packs (pure copies) ----
    for (int idx = t; idx < NI * 32; idx += 256) {
        int i = idx >> 5, c = idx & 31;
        hi[i * GSTR + c] = pk[idx];
        lo[i * GSTR + c] = pk[NI * 32 + idx];
    }
    if (t < NI) {
        const float4* pp = (const float4*)(g_prm + (size_t)(b * NI + t) * 8);
        float4 p0 = pp[0], p1 = pp[1];
        kk1[t] = p0.y;
        kk2[t] = p1.x;
        qz[t]  = make_float4(p0.x, p0.z, p0.w, p1.y);
    }
    __syncthreads();

    int rowA0 = mt * 128 + warp * 16 + g;
    int rowA1 = rowA0 + 8;
    bool v0 = rowA0 < NI, v1 = rowA1 < NI;
    int ra0 = (v0 ? rowA0 : 0) * GSTR;
    int ra1 = (v1 ? rowA1 : 0) * GSTR;

    uint32_t Ah[4][4], Al[4][4];
    #pragma unroll
    for (int s = 0; s < 4; s++) {
        int w0 = s * 8 + tg, w1 = w0 + 4;
        Ah[s][0] = v0 ? hi[ra0 + w0] : 0u;  Ah[s][1] = v1 ? hi[ra1 + w0] : 0u;
        Ah[s][2] = v0 ? hi[ra0 + w1] : 0u;  Ah[s][3] = v1 ? hi[ra1 + w1] : 0u;
        Al[s][0] = v0 ? lo[ra0 + w0] : 0u;  Al[s][1] = v1 ? lo[ra1 + w0] : 0u;
        Al[s][2] = v0 ? lo[ra0 + w1] : 0u;  Al[s][3] = v1 ? lo[ra1 + w1] : 0u;
    }

    float garr[7][4];
    #pragma unroll
    for (int k = 0; k < 7; k++) {
        if (k < cnt) {
            int jb = (nt0 + k) * JT;
            int br = (jb + g) * GSTR;
            float d0 = 0, d1 = 0, d2 = 0, d3 = 0;
            #pragma unroll
            for (int s = 0; s < 4; s++) {
                int w0 = s * 8 + tg, w1 = w0 + 4;
                uint32_t bh0 = hi[br + w0], bh1 = hi[br + w1];
                uint32_t bl0 = lo[br + w0], bl1 = lo[br + w1];
                mma_bf16(d0, d1, d2, d3, Ah[s][0], Ah[s][1], Ah[s][2], Ah[s][3], bh0, bh1);
                mma_bf16(d0, d1, d2, d3, Ah[s][0], Ah[s][1], Ah[s][2], Ah[s][3], bl0, bl1);
                mma_bf16(d0, d1, d2, d3, Al[s][0], Al[s][1], Al[s][2], Al[s][3], bh0, bh1);
            }
            garr[k][0] = d0; garr[k][1] = d1; garr[k][2] = d2; garr[k][3] = d3;
        }
    }
    __syncthreads();

    // ---- Phase B staging: w packs into SAME buffers ----
    for (int idx = t; idx < NI * 32; idx += 256) {
        int i = idx >> 5, c = idx & 31;
        hi[i * GSTR + c] = pk[2 * NI * 32 + idx];
        lo[i * GSTR + c] = pk[3 * NI * 32 + idx];
    }
    __syncthreads();

    #pragma unroll
    for (int s = 0; s < 4; s++) {
        int w0 = s * 8 + tg, w1 = w0 + 4;
        Ah[s][0] = v0 ? hi[ra0 + w0] : 0u;  Ah[s][1] = v1 ? hi[ra1 + w0] : 0u;
        Ah[s][2] = v0 ? hi[ra0 + w1] : 0u;  Ah[s][3] = v1 ? hi[ra1 + w1] : 0u;
        Al[s][0] = v0 ? lo[ra0 + w0] : 0u;  Al[s][1] = v1 ? lo[ra1 + w0] : 0u;
        Al[s][2] = v0 ? lo[ra0 + w1] : 0u;  Al[s][3] = v1 ? lo[ra1 + w1] : 0u;
    }

    #pragma unroll
    for (int k = 0; k < 7; k++) {
        if (k < cnt) {
            int nt = nt0 + k;
            int jb = nt * JT;
            int br = (jb + g) * GSTR;
            float h0 = 0, h1 = 0, h2 = 0, h3 = 0;
            #pragma unroll
            for (int s = 0; s < 4; s++) {
                int w0 = s * 8 + tg, w1 = w0 + 4;
                uint32_t bh0 = hi[br + w0], bh1 = hi[br + w1];
                uint32_t bl0 = lo[br + w0], bl1 = lo[br + w1];
                mma_bf16(h0, h1, h2, h3, Ah[s][0], Ah[s][1], Ah[s][2], Ah[s][3], bh0, bh1);
                mma_bf16(h0, h1, h2, h3, Ah[s][0], Ah[s][1], Ah[s][2], Ah[s][3], bl0, bl1);
                mma_bf16(h0, h1, h2, h3, Al[s][0], Al[s][1], Al[s][2], Al[s][3], bh0, bh1);
            }
            int j = jb + 2 * tg;
            #pragma unroll
            for (int half = 0; half < 2; half++) {
                int i = half ? rowA1 : rowA0;
                if (i < NI) {
                    float G0 = half ? garr[k][2] : garr[k][0];
                    float G1 = half ? garr[k][3] : garr[k][1];
                    float H0 = half ? h2 : h0, H1 = half ? h3 : h1;
                    float4 qv = qz[i];
                    float mu0  = G0 * (1.f / DD);
                    float var0 = fmaf(-mu0, mu0, H0 * (1.f / DD));
                    float rr0  = rsqrtf(var0 + EPS);
                    float mu1  = G1 * (1.f / DD);
                    float var1 = fmaf(-mu1, mu1, H1 * (1.f / DD));
                    float rr1  = rsqrtf(var1 + EPS);

                    float sA = qv.x + kk1[j];     sA = sA > 0.f ? sA : SLOPE * sA;
                    float a1_0 = __expf(sA) * qv.y;
                    float sB = qv.z + kk2[j];     sB = sB > 0.f ? sB : SLOPE * sB;
                    float a2_0 = __expf(sB) * qv.w;
                    sA = qv.x + kk1[j + 1];       sA = sA > 0.f ? sA : SLOPE * sA;
                    float a1_1 = __expf(sA) * qv.y;
                    sB = qv.z + kk2[j + 1];       sB = sB > 0.f ? sB : SLOPE * sB;
                    float a2_1 = __expf(sB) * qv.w;

                    int pidx = ((b * NJT + nt) * 4 + tg) * NI + i;
                    g_cT[pidx] = make_float4(a1_0 * rr0, a2_0 * rr0, a1_1 * rr1, a2_1 * rr1);
                }
            }
        }
    }
}

// =======================================================================
// k3b: 4 j-tiles per block. grid (7, BN).
#define OFF_UA   0
#define OFF_C12  13600
#define OFF_WLN  16800
#define OFF_BLN  16864
#define OFF_SC   16928
#define SMEM_FLOATS (OFF_SC + 16)
#define SMEM_BYTES  (SMEM_FLOATS * 4)

extern __shared__ float sm3[];

__global__ __launch_bounds__(256, 3)
void k3b_main(const float* __restrict__ lnw, const float* __restrict__ lnb,
              float* __restrict__ out) {
    int bt = blockIdx.x;
    int b  = blockIdx.y;
    int t  = threadIdx.x;
    int warp = t >> 5, lane = t & 31;

    float* ua_s = sm3 + OFF_UA;
    float* c12  = sm3 + OFF_C12;
    float* wln  = sm3 + OFF_WLN;
    float* bln  = sm3 + OFF_BLN;
    float* Sc   = sm3 + OFF_SC;

    const float4* uab4 = (const float4*)(g_ua + (size_t)b * NI * DD);
    for (int idx = t; idx < NI * 16; idx += 256) {
        int i = idx >> 4, c = idx & 15;
        *(float4*)(ua_s + i * 68 + c * 4) = uab4[idx];
    }
    if (t < 64) { wln[t] = lnw[t]; bln[t] = lnb[t]; }

    int tile0 = bt * 4;
    int ntile = NJT - tile0 < 4 ? NJT - tile0 : 4;

    for (int ps = 0; ps < ntile; ps++) {
        int jt = tile0 + ps;
        int jbase = jt * JT;
        if (ps) __syncthreads();

        if (t < NI) {
            size_t pbase = ((size_t)(b * NJT + jt)) * 4 * NI;
            float* crow = c12 + t * 4;
            #pragma unroll
            for (int m = 0; m < 4; m++)
                *(float4*)(crow + m * 800) = g_cT[pbase + m * NI + t];
        }
        if (t < 16) Sc[t] = g_S0[((size_t)b * NJT + jt) * 16 + t];
        __syncthreads();

        int wj    = warp & 3;
        int ihalf = warp >> 2;
        u64 a00 = 0, a01 = 0, a10 = 0, a11 = 0;
        {
            int i0 = ihalf * 100;
            const float* up = ua_s + 2 * lane;
            const float* cp = c12 + wj * 800;
            #pragma unroll 4
            for (int i = i0; i < i0 + 100; i++) {
                float2 u = *(const float2*)(up + i * 68);
                ulonglong2 cq = *(const ulonglong2*)(cp + i * 4);
                u64 ux = f2_pack(u.x, u.x);
                u64 uy = f2_pack(u.y, u.y);
                a00 = f2_fma(cq.x, ux, a00);
                a01 = f2_fma(cq.x, uy, a01);
                a10 = f2_fma(cq.y, ux, a10);
                a11 = f2_fma(cq.y, uy, a11);
            }
        }
        __syncthreads();
        u64* pbuf = (u64*)c12;
        if (ihalf == 1) {
            u64* p = pbuf + ((size_t)(wj * 32 + lane)) * 4;
            p[0] = a00; p[1] = a01; p[2] = a10; p[3] = a11;
        }
        __syncthreads();
        if (ihalf == 0) {
            const u64* p = pbuf + ((size_t)(wj * 32 + lane)) * 4;
            a00 = f2_add(a00, p[0]);
            a01 = f2_add(a01, p[1]);
            a10 = f2_add(a10, p[2]);
            a11 = f2_add(a11, p[3]);
            float2 wl = *(const float2*)(wln + 2 * lane);
            float2 bl = *(const float2*)(bln + 2 * lane);
            #pragma unroll
            for (int k = 0; k < 2; k++) {
                int jj = 2 * wj + k;
                u64 S1x = k ? a10 : a00;
                u64 S1y = k ? a11 : a01;
                int j = jbase + jj;
                float2 uj = *(const float2*)(ua_s + j * 68 + 2 * lane);
                u64 ujx = f2_pack(uj.x, uj.x);
                u64 ujy = f2_pack(uj.y, uj.y);

                u64 pr = f2_fma(ujy, S1y, f2_mul(ujx, S1x));
                float pa, pb;
                f2_unpack(pr, pa, pb);
                #pragma unroll
                for (int o = 16; o > 0; o >>= 1) {
                    pa += __shfl_xor_sync(0xffffffffu, pa, o);
                    pb += __shfl_xor_sync(0xffffffffu, pb, o);
                }
                float S2a = pa * (1.f / DD), S2b = pb * (1.f / DD);

                u64 S0  = f2_pack(Sc[jj * 2 + 0], Sc[jj * 2 + 1]);
                u64 S2n = f2_pack(-S2a, -S2b);
                u64 X  = f2_fma(ujx, S1x, S2n);
                u64 at = f2_fma(f2_pack(bl.x, bl.x), S0, f2_mul(f2_pack(wl.x, wl.x), X));
                float t1, t2;
                f2_unpack(at, t1, t2);
                float ox = 0.5f * (t1 + t2);
                X  = f2_fma(ujy, S1y, S2n);
                at = f2_fma(f2_pack(bl.y, bl.y), S0, f2_mul(f2_pack(wl.y, wl.y), X));
                f2_unpack(at, t1, t2);
                float oy = 0.5f * (t1 + t2);
                ox = ox > 0.f ? ox : SLOPE * ox;
                oy = oy > 0.f ? oy : SLOPE * oy;
                *(float2*)(out + (size_t)(b * 201 + 1 + j) * DD + 2 * lane) = make_float2(ox, oy);
            }
        }
    }
}

// ---------------- launch ----------------
extern "C" void kernel_launch(void* const* d_in, const int* in_sizes, int n_in,
                              void* d_out, int out_size) {
    const float* emb = (const float*)d_in[0];
    const float* lnw = (const float*)d_in[1];
    const float* lnb = (const float*)d_in[2];
    const float* W1  = (const float*)d_in[3];
    const float* W1b = (const float*)d_in[4];
    const float* W2  = (const float*)d_in[5];
    const float* W2b = (const float*)d_in[6];
    const float* a1  = (const float*)d_in[7];
    const float* a1b = (const float*)d_in[8];
    const float* a2  = (const float*)d_in[9];
    const float* a2b = (const float*)d_in[10];
    float* out = (float*)d_out;
    (void)in_sizes; (void)n_in; (void)out_size;

    cudaFuncSetAttribute(kA1_prep, cudaFuncAttributeMaxDynamicSharedMemorySize, B_BYTES);
    cudaFuncSetAttribute(k3a_gram, cudaFuncAttributeMaxDynamicSharedMemorySize, GA_BYTES);
    cudaFuncSetAttribute(k3b_main, cudaFuncAttributeMaxDynamicSharedMemorySize, SMEM_BYTES);

    dim3 gA1(2, BN);
    kA1_prep<<<gA1, 256, B_BYTES>>>(emb, lnw, lnb, W1, W1b, W2, W2b,
                                    a1, a1b, a2, a2b, out);
    dim3 gA2(4, BN);
    kA2_z<<<gA2, 256>>>();
    kA3_s0<<<gA2, 256>>>();
    dim3 gG(2, 4, BN);
    k3a_gram<<<gG, 256, GA_BYTES>>>();
    dim3 g3(7, BN);
    k3b_main<<<g3, 256, SMEM_BYTES>>>(lnw, lnb, out);
}

// round 17
// speedup vs baseline: 1.2327x; 1.2327x over previous
#include <cuda_runtime.h>
#include <math.h>

#define BN    32
#define NODES 202
#define NI    200
#define DD    64
#define JT    8
#define NJT   25
#define EPS   1e-5f
#define SLOPE 0.01f

typedef unsigned long long u64;

// ---- packed fp32x2 helpers (sm_103a) ----
__device__ __forceinline__ u64 f2_mul(u64 a, u64 b) {
    u64 r; asm("mul.rn.f32x2 %0,%1,%2;" : "=l"(r) : "l"(a), "l"(b)); return r;
}
__device__ __forceinline__ u64 f2_add(u64 a, u64 b) {
    u64 r; asm("add.rn.f32x2 %0,%1,%2;" : "=l"(r) : "l"(a), "l"(b)); return r;
}
__device__ __forceinline__ u64 f2_fma(u64 a, u64 b, u64 c) {
    u64 r; asm("fma.rn.f32x2 %0,%1,%2,%3;" : "=l"(r) : "l"(a), "l"(b), "l"(c)); return r;
}
__device__ __forceinline__ u64 f2_pack(float lo, float hi) {
    u64 r; asm("mov.b64 %0,{%1,%2};" : "=l"(r) : "f"(lo), "f"(hi)); return r;
}
__device__ __forceinline__ void f2_unpack(u64 v, float& lo, float& hi) {
    asm("mov.b64 {%0,%1},%2;" : "=f"(lo), "=f"(hi) : "l"(v));
}

// ---------------- device scratch ----------------
__device__ float g_ua[BN * NI * DD];
__device__ float g_qk[BN * 4 * NI];      // [b][0:q1 1:k1 2:q2 3:k2][i]
__device__ float g_prm[BN * NI * 8];     // (q1,k1,iZ1,q2),(k2,iZ2,_,_)
__device__ float g_S0[BN * NJT * 16];    // Sc layout: [jj*2+head]

// =======================================================================
// kA1: per-batch-half prep. grid (2, BN), 256 threads.  (R8 proven)
#define B_W    0
#define B_A    8192
#define B_WB   8576
#define B_LNW  8704
#define B_LNB  8768
#define B_RAW  8832
#define B_UA   15768
#define B_MU   22568
#define B_RS   22670
#define B_UID  22772
#define B_IID  22836
#define B_VQ   22900
#define B_VK   23028
#define B_RED  23156
#define B_CQK  23164
#define B_QC   23170
#define B_KC   23172
#define B_FLOATS 23174
#define B_BYTES  (B_FLOATS * 4)

extern __shared__ float smB[];

__global__ __launch_bounds__(256, 1)
void kA1_prep(const float* __restrict__ emb,
              const float* __restrict__ lnw, const float* __restrict__ lnb,
              const float* __restrict__ W1, const float* __restrict__ W1b,
              const float* __restrict__ W2, const float* __restrict__ W2b,
              const float* __restrict__ a1, const float* __restrict__ a1b,
              const float* __restrict__ a2, const float* __restrict__ a2b,
              float* __restrict__ out) {
    int h    = blockIdx.x;
    int b    = blockIdx.y;
    int t    = threadIdx.x;
    int warp = t >> 5, lane = t & 31;

    float* W_s   = smB + B_W;
    float* a_s   = smB + B_A;
    float* wb_s  = smB + B_WB;
    float* lnw_s = smB + B_LNW;
    float* lnb_s = smB + B_LNB;
    float* raw   = smB + B_RAW;
    float* ua_s  = smB + B_UA;
    float* mu_s  = smB + B_MU;
    float* rs_s  = smB + B_RS;
    float* uid   = smB + B_UID;
    float* iid   = smB + B_IID;
    float* vq_s  = smB + B_VQ;
    float* vk_s  = smB + B_VK;
    float* red   = smB + B_RED;
    float* cqk   = smB + B_CQK;
    float* qc_s  = smB + B_QC;
    float* kc_s  = smB + B_KC;

    for (int idx = t; idx < 2048; idx += 256) {
        int hh = idx >> 10;
        ((float4*)W_s)[idx] = ((const float4*)(hh ? W2 : W1))[idx & 1023];
    }
    for (int idx = t; idx < 384; idx += 256)
        a_s[idx] = (idx < 192) ? a1[idx] : a2[idx - 192];
    if (t < 128) wb_s[t] = (t < 64) ? W1b[t] : W2b[t - 64];
    if (t < 64) { lnw_s[t] = lnw[t]; lnb_s[t] = lnb[t]; }
    const float4* e4 = (const float4*)(emb + (size_t)b * NODES * DD);
    for (int idx = t; idx < 102 * 16; idx += 256) {
        int r = idx >> 4, c = idx & 15;
        int g = (r < 2) ? r : r + 100 * h;
        *(float4*)(raw + r * 68 + c * 4) = e4[g * 16 + c];
    }
    __syncthreads();

    if (t < 102) {
        const float* rp = raw + t * 68;
        float s = 0.f, ss = 0.f;
        #pragma unroll
        for (int c = 0; c < 16; c++) {
            float4 v = *(const float4*)(rp + c * 4);
            s += (v.x + v.y) + (v.z + v.w);
            ss = fmaf(v.x, v.x, fmaf(v.y, v.y, fmaf(v.z, v.z, fmaf(v.w, v.w, ss))));
        }
        float m = s * (1.f / DD);
        float var = fmaf(-m, m, ss * (1.f / DD));
        mu_s[t] = m;
        rs_s[t] = rsqrtf(var + EPS);
    }
    if (t >= 208 && t < 214) {
        int idx = t - 208, hh = idx / 3, wch = idx % 3;
        float s = 0.f;
        #pragma unroll 8
        for (int o = 0; o < DD; o++)
            s = fmaf(a_s[hh * 192 + wch * 64 + o], wb_s[hh * 64 + o], s);
        cqk[idx] = s;
    }
    __syncthreads();

    if (t < 128) {
        int rw = t >> 6, d = t & 63;
        float v = fmaf((raw[rw * 68 + d] - mu_s[rw]) * rs_s[rw], lnw_s[d], lnb_s[d]);
        (rw ? iid : uid)[d] = v;
    }
    __syncthreads();
    if (h == 0 && t < DD) {
        float u = uid[t] * iid[t];
        out[(size_t)(b * 201) * DD + t] = u > 0.f ? u : SLOPE * u;
    }

    for (int idx = t; idx < 100 * 16; idx += 256) {
        int r = idx >> 4, c = idx & 15;
        float4 v = *(const float4*)(raw + (r + 2) * 68 + c * 4);
        float m = mu_s[r + 2], sc = rs_s[r + 2];
        float4 w4 = *(const float4*)(lnw_s + c * 4);
        float4 b4 = *(const float4*)(lnb_s + c * 4);
        float4 u4 = *(const float4*)(uid + c * 4);
        float4 o4;
        o4.x = fmaf((v.x - m) * sc, w4.x, b4.x) * u4.x;
        o4.y = fmaf((v.y - m) * sc, w4.y, b4.y) * u4.y;
        o4.z = fmaf((v.z - m) * sc, w4.z, b4.z) * u4.z;
        o4.w = fmaf((v.w - m) * sc, w4.w, b4.w) * u4.w;
        *(float4*)(ua_s + r * 68 + c * 4) = o4;
        ((float4*)(g_ua + ((size_t)b * NI + 100 * h + r) * DD))[c] = o4;
    }
    __syncthreads();

    if (t < 128) {
        int hh = t >> 6, d = t & 63;
        const float* Wp = W_s + hh * 4096 + d;
        const float* ap = a_s + hh * 192;
        float sqv = 0.f, skv = 0.f, siv = 0.f;
        #pragma unroll 8
        for (int o = 0; o < DD; o++) {
            float wv = Wp[o * 64];
            sqv = fmaf(ap[o],       wv, sqv);
            skv = fmaf(ap[64 + o],  wv, skv);
            siv = fmaf(ap[128 + o], wv, siv);
        }
        vq_s[hh * 64 + d] = sqv;
        vk_s[hh * 64 + d] = skv;
        float viid = siv * iid[d];
        #pragma unroll
        for (int o = 16; o > 0; o >>= 1) viid += __shfl_xor_sync(0xffffffffu, viid, o);
        if (lane == 0) red[warp] = viid;
    }
    __syncthreads();
    if (t == 0) {
        qc_s[0] = red[0] + red[1] + cqk[0] + cqk[2] + a1b[0];
        kc_s[0] = cqk[1];
        qc_s[1] = red[2] + red[3] + cqk[3] + cqk[5] + a2b[0];
        kc_s[1] = cqk[4];
    }
    __syncthreads();

    if (t < 100) {
        const float* u = ua_s + t * 68;
        float s10 = 0, s20 = 0, s11 = 0, s21 = 0;
        #pragma unroll
        for (int c = 0; c < 16; c++) {
            float4 uv = *(const float4*)(u + c * 4);
            float4 q0 = *(const float4*)(vq_s + c * 4);
            float4 k0 = *(const float4*)(vk_s + c * 4);
            float4 q1v = *(const float4*)(vq_s + 64 + c * 4);
            float4 k1v = *(const float4*)(vk_s + 64 + c * 4);
            s10 = fmaf(uv.x, q0.x, fmaf(uv.y, q0.y, fmaf(uv.z, q0.z, fmaf(uv.w, q0.w, s10))));
            s20 = fmaf(uv.x, k0.x, fmaf(uv.y, k0.y, fmaf(uv.z, k0.z, fmaf(uv.w, k0.w, s20))));
            s11 = fmaf(uv.x, q1v.x, fmaf(uv.y, q1v.y, fmaf(uv.z, q1v.z, fmaf(uv.w, q1v.w, s11))));
            s21 = fmaf(uv.x, k1v.x, fmaf(uv.y, k1v.y, fmaf(uv.z, k1v.z, fmaf(uv.w, k1v.w, s21))));
        }
        int i = 100 * h + t;
        float* gq = g_qk + (size_t)b * 800;
        gq[i]       = s10 + qc_s[0];
        gq[200 + i] = s20 + kc_s[0];
        gq[400 + i] = s11 + qc_s[1];
        gq[600 + i] = s21 + kc_s[1];
    }
}

// =======================================================================
// kA2: softmax Z. grid (4, BN). (R8 proven)
__global__ __launch_bounds__(256, 8)
void kA2_z() {
    __shared__ float s_qk[800];
    __shared__ float zp[400];
    int q = blockIdx.x;
    int b = blockIdx.y;
    int t = threadIdx.x;

    const float* gq = g_qk + (size_t)b * 800;
    for (int idx = t; idx < 800; idx += 256) s_qk[idx] = gq[idx];
    __syncthreads();

    if (t < 200) {
        int seg = t / 50, il = t % 50;
        int i = q * 50 + il;
        float q1 = s_qk[i], q2 = s_qk[400 + i];
        float Z1 = 0.f, Z2 = 0.f;
        int j0 = seg * 50;
        #pragma unroll 5
        for (int jj = 0; jj < 50; jj++) {
            int j = j0 + jj;
            float s = q1 + s_qk[200 + j]; s = s > 0.f ? s : SLOPE * s; Z1 += __expf(s);
            float r = q2 + s_qk[600 + j]; r = r > 0.f ? r : SLOPE * r; Z2 += __expf(r);
        }
        zp[seg * 50 + il]       = Z1;
        zp[200 + seg * 50 + il] = Z2;
    }
    __syncthreads();
    if (t < 50) {
        int i = q * 50 + t;
        float Z1 = zp[t] + zp[50 + t] + zp[100 + t] + zp[150 + t];
        float Z2 = zp[200 + t] + zp[250 + t] + zp[300 + t] + zp[350 + t];
        float4* p = (float4*)(g_prm + (size_t)(b * NI + i) * 8);
        p[0] = make_float4(s_qk[i], s_qk[200 + i], 1.f / Z1, s_qk[400 + i]);
        p[1] = make_float4(s_qk[600 + i], 1.f / Z2, 0.f, 0.f);
    }
}

// =======================================================================
// kA3: S0[j] = sum_i alpha_ij  (column sums).  grid (4, BN).  (validated R13-16)
__global__ __launch_bounds__(256, 8)
void kA3_s0() {
    __shared__ float s_qk[800];
    __shared__ float s_iz[400];
    __shared__ float zp[400];
    int q = blockIdx.x;
    int b = blockIdx.y;
    int t = threadIdx.x;

    const float* gq = g_qk + (size_t)b * 800;
    for (int idx = t; idx < 800; idx += 256) s_qk[idx] = gq[idx];
    if (t < 200) {
        const float4* pp = (const float4*)(g_prm + (size_t)(b * NI + t) * 8);
        s_iz[t]       = pp[0].z;
        s_iz[200 + t] = pp[1].y;
    }
    __syncthreads();

    if (t < 200) {
        int seg = t / 50, jl = t % 50;
        int j = q * 50 + jl;
        float k1 = s_qk[200 + j], k2 = s_qk[600 + j];
        float S1 = 0.f, S2 = 0.f;
        int i0 = seg * 50;
        #pragma unroll 5
        for (int ii = 0; ii < 50; ii++) {
            int i = i0 + ii;
            float s = s_qk[i] + k1;       s = s > 0.f ? s : SLOPE * s;
            S1 = fmaf(__expf(s), s_iz[i], S1);
            float r = s_qk[400 + i] + k2; r = r > 0.f ? r : SLOPE * r;
            S2 = fmaf(__expf(r), s_iz[200 + i], S2);
        }
        zp[seg * 50 + jl]       = S1;
        zp[200 + seg * 50 + jl] = S2;
    }
    __syncthreads();
    if (t < 100) {
        int head = t / 50, jl = t % 50;
        int j = q * 50 + jl;
        int o = head * 200;
        float S = zp[o + jl] + zp[o + 50 + jl] + zp[o + 100 + jl] + zp[o + 150 + jl];
        g_S0[((size_t)b * NJT + (j >> 3)) * 16 + (j & 7) * 2 + head] = S;
    }
}

// =======================================================================
// K3: R8's proven kernel, minus the S0 reduction tree (Sc from g_S0).
#define OFF_UA   0
#define OFF_KK1  13600
#define OFF_KK2  13800
#define OFF_C12  14000     // 4 planes * 800 = 3200
#define OFF_WLN  17200
#define OFF_BLN  17264
#define OFF_SC   17328     // 16
#define SMEM_FLOATS (OFF_SC + 16)   // 17344
#define SMEM_BYTES  (SMEM_FLOATS * 4)

extern __shared__ float sm3[];

__global__ __launch_bounds__(256, 3)
void k3_main(const float* __restrict__ lnw, const float* __restrict__ lnb,
             float* __restrict__ out) {
    int jt = blockIdx.x;
    int b  = blockIdx.y;
    int t  = threadIdx.x;
    int warp = t >> 5, lane = t & 31;

    float* ua_s = sm3 + OFF_UA;     // stride 68
    float* kk1  = sm3 + OFF_KK1;
    float* kk2  = sm3 + OFF_KK2;
    float* c12  = sm3 + OFF_C12;    // planes of 800
    float* wln  = sm3 + OFF_WLN;
    float* bln  = sm3 + OFF_BLN;
    float* Sc   = sm3 + OFF_SC;

    const float4* uab4 = (const float4*)(g_ua + (size_t)b * NI * DD);
    for (int idx = t; idx < NI * 16; idx += 256) {
        int i = idx >> 4, c = idx & 15;
        *(float4*)(ua_s + i * 68 + c * 4) = uab4[idx];
    }
    if (t < 64) { wln[t] = lnw[t]; bln[t] = lnb[t]; }
    if (t < 16) Sc[t] = g_S0[((size_t)b * NJT + blockIdx.x) * 16 + t];

    float q1 = 0, iZ1 = 0, q2 = 0, iZ2 = 0;
    if (t < NI) {
        const float4* pp = (const float4*)(g_prm + (size_t)(b * NI + t) * 8);
        float4 p0 = pp[0], p1 = pp[1];
        q1 = p0.x; kk1[t] = p0.y; iZ1 = p0.z; q2 = p0.w;
        kk2[t] = p1.x; iZ2 = p1.y;
    }
    __syncthreads();

    int jbase = jt * JT;

    // ---- phase 1: Gram stats (packed f32x2, j-register-tiled) ----
    u64 s1p[JT], s2p[JT];
    #pragma unroll
    for (int jj = 0; jj < JT; jj++) { s1p[jj] = 0ull; s2p[jj] = 0ull; }

    if (t < NI) {
        const float* ui = ua_s + t * 68;
        const float* ujb = ua_s + jbase * 68;
        #pragma unroll 4
        for (int dc = 0; dc < 16; dc++) {
            ulonglong2 u = *(const ulonglong2*)(ui + dc * 4);
            #pragma unroll
            for (int jj = 0; jj < JT; jj++) {
                ulonglong2 v = *(const ulonglong2*)(ujb + jj * 68 + dc * 4);  // broadcast
                u64 p0 = f2_mul(u.x, v.x);
                u64 p1 = f2_mul(u.y, v.y);
                s1p[jj] = f2_add(s1p[jj], p0);
                s1p[jj] = f2_add(s1p[jj], p1);
                s2p[jj] = f2_fma(p0, p0, s2p[jj]);
                s2p[jj] = f2_fma(p1, p1, s2p[jj]);
            }
        }

        float cst[2 * JT];
        #pragma unroll
        for (int jj = 0; jj < JT; jj++) {
            float l1, h1, l2, h2;
            f2_unpack(s1p[jj], l1, h1);
            f2_unpack(s2p[jj], l2, h2);
            float mu  = (l1 + h1) * (1.f / DD);
            float var = fmaf(-mu, mu, (l2 + h2) * (1.f / DD));
            float rr  = rsqrtf(var + EPS);
            int j = jbase + jj;
            float s = q1 + kk1[j]; s = s > 0.f ? s : SLOPE * s;
            float c1 = __expf(s) * iZ1 * rr;
            s = q2 + kk2[j]; s = s > 0.f ? s : SLOPE * s;
            float c2 = __expf(s) * iZ2 * rr;
            cst[jj * 2 + 0] = c1; cst[jj * 2 + 1] = c2;
        }
        float* crow = c12 + t * 4;
        #pragma unroll
        for (int k = 0; k < 4; k++)
            *(float4*)(crow + k * 800) = make_float4(cst[k*4], cst[k*4+1], cst[k*4+2], cst[k*4+3]);
    }
    __syncthreads();

    // ---- phase 2: warp (wj, ihalf) ----
    int wj    = warp & 3;
    int ihalf = warp >> 2;
    u64 a00 = 0, a01 = 0, a10 = 0, a11 = 0;
    {
        int i0 = ihalf * 100;
        const float* up = ua_s + 2 * lane;
        const float* cp = c12 + wj * 800;
        #pragma unroll 4
        for (int i = i0; i < i0 + 100; i++) {
            float2 u = *(const float2*)(up + i * 68);
            ulonglong2 cq = *(const ulonglong2*)(cp + i * 4);
            u64 ux = f2_pack(u.x, u.x);
            u64 uy = f2_pack(u.y, u.y);
            a00 = f2_fma(cq.x, ux, a00);
            a01 = f2_fma(cq.x, uy, a01);
            a10 = f2_fma(cq.y, ux, a10);
            a11 = f2_fma(cq.y, uy, a11);
        }
    }
    __syncthreads();
    u64* pbuf = (u64*)c12;
    if (ihalf == 1) {
        u64* p = pbuf + ((size_t)(wj * 32 + lane)) * 4;
        p[0] = a00; p[1] = a01; p[2] = a10; p[3] = a11;
    }
    __syncthreads();
    if (ihalf == 0) {
        const u64* p = pbuf + ((size_t)(wj * 32 + lane)) * 4;
        a00 = f2_add(a00, p[0]);
        a01 = f2_add(a01, p[1]);
        a10 = f2_add(a10, p[2]);
        a11 = f2_add(a11, p[3]);
        float2 wl = *(const float2*)(wln + 2 * lane);
        float2 bl = *(const float2*)(bln + 2 * lane);
        #pragma unroll
        for (int k = 0; k < 2; k++) {
            int jj = 2 * wj + k;
            u64 S1x = k ? a10 : a00;
            u64 S1y = k ? a11 : a01;
            int j = jbase + jj;
            float2 uj = *(const float2*)(ua_s + j * 68 + 2 * lane);
            u64 ujx = f2_pack(uj.x, uj.x);
            u64 ujy = f2_pack(uj.y, uj.y);

            u64 pr = f2_fma(ujy, S1y, f2_mul(ujx, S1x));
            float pa, pb;
            f2_unpack(pr, pa, pb);
            #pragma unroll
            for (int o = 16; o > 0; o >>= 1) {
                pa += __shfl_xor_sync(0xffffffffu, pa, o);
                pb += __shfl_xor_sync(0xffffffffu, pb, o);
            }
            float S2a = pa * (1.f / DD), S2b = pb * (1.f / DD);

            u64 S0  = f2_pack(Sc[jj * 2 + 0], Sc[jj * 2 + 1]);
            u64 S2n = f2_pack(-S2a, -S2b);
            u64 X  = f2_fma(ujx, S1x, S2n);
            u64 at = f2_fma(f2_pack(bl.x, bl.x), S0, f2_mul(f2_pack(wl.x, wl.x), X));
            float t1, t2;
            f2_unpack(at, t1, t2);
            float ox = 0.5f * (t1 + t2);
            X  = f2_fma(ujy, S1y, S2n);
            at = f2_fma(f2_pack(bl.y, bl.y), S0, f2_mul(f2_pack(wl.y, wl.y), X));
            f2_unpack(at, t1, t2);
            float oy = 0.5f * (t1 + t2);
            ox = ox > 0.f ? ox : SLOPE * ox;
            oy = oy > 0.f ? oy : SLOPE * oy;
            *(float2*)(out + (size_t)(b * 201 + 1 + j) * DD + 2 * lane) = make_float2(ox, oy);
        }
    }
}

// ---------------- launch ----------------
extern "C" void kernel_launch(void* const* d_in, const int* in_sizes, int n_in,
                              void* d_out, int out_size) {
    const float* emb = (const float*)d_in[0];
    const float* lnw = (const float*)d_in[1];
    const float* lnb = (const float*)d_in[2];
    const float* W1  = (const float*)d_in[3];
    const float* W1b = (const float*)d_in[4];
    const float* W2  = (const float*)d_in[5];
    const float* W2b = (const float*)d_in[6];
    const float* a1  = (const float*)d_in[7];
    const float* a1b = (const float*)d_in[8];
    const float* a2  = (const float*)d_in[9];
    const float* a2b = (const float*)d_in[10];
    float* out = (float*)d_out;
    (void)in_sizes; (void)n_in; (void)out_size;

    cudaFuncSetAttribute(kA1_prep, cudaFuncAttributeMaxDynamicSharedMemorySize, B_BYTES);
    cudaFuncSetAttribute(k3_main, cudaFuncAttributeMaxDynamicSharedMemorySize, SMEM_BYTES);

    dim3 gA1(2, BN);
    kA1_prep<<<gA1, 256, B_BYTES>>>(emb, lnw, lnb, W1, W1b, W2, W2b,
                                    a1, a1b, a2, a2b, out);
    dim3 gA2(4, BN);
    kA2_z<<<gA2, 256>>>();
    kA3_s0<<<gA2, 256>>>();
    dim3 g3(NJT, BN);
    k3_main<<<g3, 256, SMEM_BYTES>>>(lnw, lnb, out);
}